// round 14
// baseline (speedup 1.0000x reference)
#include <cuda_runtime.h>
#include <cuda_fp16.h>
#include <cstdint>

#define NB 16
#define NN 32768          // nodes = 128*256 torus
#define HH 64
#define NDOUT 128
#define MROWS (NB*NN)     // 524288
#define EPSBN 1e-5f
#define RB 272            // As row bytes: 256 data + 16 pad -> conflict-free ldmatrix
#define TPC 4
#define ABUF1 (128*RB)    // 34816
#define ABUF2 (64*RB)     // 17408

// ---------------- scratch (feature-major layout: [b][f][n]) ----------------
__device__ __half g_h[NB*HH*NN];     // trunk ping
__device__ __half g_h2[NB*HH*NN];    // trunk pong
__device__ __half g_agg[NB*HH*NN];   // stencil aggregate (gemm1 input)
__device__ __half g_y[NB*HH*NN];     // gemm outputs (pre-BN), fp16; stats from fp32 accs
__device__ float  g_stats[6][2*HH];
__device__ float  g_pool[NB*HH];

// ---------------- helpers ---------------------------------------------------
__device__ __forceinline__ float2 h2f(uint32_t u) {
    __half2 h = *(__half2*)&u;
    return __half22float2(h);
}
__device__ __forceinline__ uint32_t f2h(float a, float b) {
    __half2 h = __floats2half2_rn(a, b);
    return *(uint32_t*)&h;
}
__device__ __forceinline__ void u4tof8(uint4 u, float* f) {
    float2 a = h2f(u.x), b = h2f(u.y), c = h2f(u.z), d = h2f(u.w);
    f[0] = a.x; f[1] = a.y; f[2] = b.x; f[3] = b.y;
    f[4] = c.x; f[5] = c.y; f[6] = d.x; f[7] = d.y;
}
__device__ __forceinline__ uint4 f8tou4(const float* f) {
    uint4 u;
    u.x = f2h(f[0], f[1]); u.y = f2h(f[2], f[3]);
    u.z = f2h(f[4], f[5]); u.w = f2h(f[6], f[7]);
    return u;
}
__device__ __forceinline__ void mma_f16(float* d, const uint4& a, uint32_t b0, uint32_t b1) {
    asm volatile(
        "mma.sync.aligned.m16n8k16.row.col.f32.f16.f16.f32 "
        "{%0,%1,%2,%3}, {%4,%5,%6,%7}, {%8,%9}, {%0,%1,%2,%3};"
        : "+f"(d[0]), "+f"(d[1]), "+f"(d[2]), "+f"(d[3])
        : "r"(a.x), "r"(a.y), "r"(a.z), "r"(a.w), "r"(b0), "r"(b1));
}
#define LDMX4T(r0, r1, r2, r3, addr) \
    asm volatile("ldmatrix.sync.aligned.m8n8.x4.trans.shared.b16 {%0,%1,%2,%3}, [%4];" \
        : "=r"(r0), "=r"(r1), "=r"(r2), "=r"(r3) : "r"(addr))
__device__ __forceinline__ void bn_coef(int use, int f, const float* g, const float* be,
                                        float& sc, float& sh) {
    const float invM = 1.f / (float)MROWS;
    float s = g_stats[use][f], q = g_stats[use][HH + f];
    float m = s * invM;
    float v = q * invM - m * m;
    float r = rsqrtf(v + EPSBN);
    sc = g[f] * r;
    sh = fmaf(-m, sc, be[f]);
}
__device__ __forceinline__ void cpa16(uint32_t dst, const void* src) {
    asm volatile("cp.async.cg.shared.global [%0], [%1], 16;" :: "r"(dst), "l"(src));
}
__device__ __forceinline__ void cpcommit() { asm volatile("cp.async.commit_group;"); }
__device__ __forceinline__ void cpwaitn(int n) {
    switch (n) {
        case 0: asm volatile("cp.async.wait_group 0;"); break;
        case 1: asm volatile("cp.async.wait_group 1;"); break;
        case 2: asm volatile("cp.async.wait_group 2;"); break;
        case 3: asm volatile("cp.async.wait_group 3;"); break;
        case 4: asm volatile("cp.async.wait_group 4;"); break;
        case 5: asm volatile("cp.async.wait_group 5;"); break;
        case 6: asm volatile("cp.async.wait_group 6;"); break;
        default: asm volatile("cp.async.wait_group 7;"); break;
    }
}

// ---------------- small kernels ---------------------------------------------
__global__ void zero_kernel() {
    int tid = threadIdx.x;
    float* s = &g_stats[0][0];
    for (int i = tid; i < 6 * 2 * HH; i += 256) s[i] = 0.f;
    for (int i = tid; i < NB * HH; i += 256) g_pool[i] = 0.f;
}

// fused embedding + initial stencil: h = relu(emb(x)); agg = 0.25*sum(nbrs(h))
// halo h values recomputed from x (x is 6.3MB -> L2-resident; recompute is free)
__global__ void embed_agg_kernel(const float* __restrict__ x,
                                 const float* __restrict__ W,
                                 const float* __restrict__ bias) {
    int b = blockIdx.z, f = blockIdx.y;
    float w0 = W[f], w1 = W[HH + f], w2 = W[2 * HH + f], bb = bias[f];
    int n = blockIdx.x * 2048 + threadIdx.x * 8;
    const float* xb = x + (size_t)(b * 3) * NN;

    auto emb1 = [&](int idx) {
        return fmaxf(fmaf(xb[idx], w0, fmaf(xb[NN + idx], w1,
                     fmaf(xb[2 * NN + idx], w2, bb))), 0.f);
    };
    auto emb8 = [&](int idx, float* r) {
#pragma unroll
        for (int h = 0; h < 2; h++) {
            float4 a = *(const float4*)(xb + idx + h * 4);
            float4 c = *(const float4*)(xb + NN + idx + h * 4);
            float4 d = *(const float4*)(xb + 2 * NN + idx + h * 4);
            r[h*4+0] = fmaxf(fmaf(a.x, w0, fmaf(c.x, w1, fmaf(d.x, w2, bb))), 0.f);
            r[h*4+1] = fmaxf(fmaf(a.y, w0, fmaf(c.y, w1, fmaf(d.y, w2, bb))), 0.f);
            r[h*4+2] = fmaxf(fmaf(a.z, w0, fmaf(c.z, w1, fmaf(d.z, w2, bb))), 0.f);
            r[h*4+3] = fmaxf(fmaf(a.w, w0, fmaf(c.w, w1, fmaf(d.w, w2, bb))), 0.f);
        }
    };

    float c[8], u[8], d[8], o[8];
    emb8(n, c);
    emb8((n + 256) & 32767, u);
    emb8((n - 256) & 32767, d);
    int base = n & ~255, z0 = n & 255;
    float lf = emb1(base | ((z0 - 1) & 255));
    float rt = emb1(base | ((z0 + 8) & 255));
#pragma unroll
    for (int j = 0; j < 8; j++) {
        float L = (j == 0) ? lf : c[j - 1];
        float R = (j == 7) ? rt : c[j + 1];
        o[j] = 0.25f * (u[j] + d[j] + L + R);
    }
    size_t plane = (size_t)(b * HH + f) * NN;
    *(uint4*)(g_h + plane + n) = f8tou4(c);
    *(uint4*)(g_agg + plane + n) = f8tou4(o);
}

// ---------------- fused: h_out = h_in + relu(bn(y)); agg = stencil(h_out) ---
__global__ __launch_bounds__(256) void fused_res_agg(int hselIn,
                                                     const float* __restrict__ gamma,
                                                     const float* __restrict__ beta,
                                                     int use) {
    __shared__ float hb[8704];
    __shared__ float ss[2];
    int b = blockIdx.z, f = blockIdx.y, tid = threadIdx.x;
    if (tid == 0) {
        float sc, sh;
        bn_coef(use, f, gamma, beta, sc, sh);
        ss[0] = sc; ss[1] = sh;
    }
    __syncthreads();
    float sc = ss[0], sh = ss[1];
    const __half* hin = hselIn ? g_h2 : g_h;
    __half* hout = hselIn ? g_h : g_h2;
    size_t plane = (size_t)(b * HH + f) * NN;
    int n0 = blockIdx.x * 8192;

    for (int q8 = tid; q8 < 1088; q8 += 256) {
        int nh = (n0 - 256 + q8 * 8) & 32767;
        float hf[8], yf[8];
        u4tof8(*(const uint4*)(hin + plane + nh), hf);
        u4tof8(*(const uint4*)(g_y + plane + nh), yf);
#pragma unroll
        for (int j = 0; j < 8; j++) hf[j] += fmaxf(fmaf(yf[j], sc, sh), 0.f);
        *(float4*)&hb[q8 * 8] = make_float4(hf[0], hf[1], hf[2], hf[3]);
        *(float4*)&hb[q8 * 8 + 4] = make_float4(hf[4], hf[5], hf[6], hf[7]);
        if (q8 >= 32 && q8 < 1056) *(uint4*)(hout + plane + nh) = f8tou4(hf);
    }
    __syncthreads();
    for (int q8 = tid; q8 < 1024; q8 += 256) {
        int i = 256 + q8 * 8;
        int n = n0 + q8 * 8;
        float o[8];
#pragma unroll
        for (int j = 0; j < 8; j++) {
            int zj = (n + j) & 255;
            int rowbase = i + j - zj;
            float lf = hb[rowbase + ((zj + 255) & 255)];
            float rt = hb[rowbase + ((zj + 1) & 255)];
            o[j] = 0.25f * (hb[i + j - 256] + hb[i + j + 256] + lf + rt);
        }
        *(uint4*)(g_agg + plane + n) = f8tou4(o);
    }
}

// ---------------- final layer: pool(h_in + relu(bn(y))), no h write ---------
__global__ __launch_bounds__(256) void relu_pool(int hselIn,
                                                 const float* __restrict__ gamma,
                                                 const float* __restrict__ beta,
                                                 int use) {
    __shared__ float ss[2];
    __shared__ float wsum[8];
    int b = blockIdx.z, f = blockIdx.y, tid = threadIdx.x;
    if (tid == 0) {
        float sc, sh;
        bn_coef(use, f, gamma, beta, sc, sh);
        ss[0] = sc; ss[1] = sh;
    }
    __syncthreads();
    float sc = ss[0], sh = ss[1];
    const __half* hin = hselIn ? g_h2 : g_h;
    size_t plane = (size_t)(b * HH + f) * NN;
    int n0 = blockIdx.x * 8192;
    float ps = 0.f;
    for (int q8 = tid; q8 < 1024; q8 += 256) {
        int n = n0 + q8 * 8;
        float hf[8], yf[8];
        u4tof8(*(const uint4*)(hin + plane + n), hf);
        u4tof8(*(const uint4*)(g_y + plane + n), yf);
#pragma unroll
        for (int j = 0; j < 8; j++) ps += hf[j] + fmaxf(fmaf(yf[j], sc, sh), 0.f);
    }
#pragma unroll
    for (int off = 16; off; off >>= 1) ps += __shfl_down_sync(0xffffffffu, ps, off);
    if ((tid & 31) == 0) wsum[tid >> 5] = ps;
    __syncthreads();
    if (tid == 0) {
        float t = 0.f;
#pragma unroll
        for (int w = 0; w < 8; w++) t += wsum[w];
        atomicAdd(&g_pool[b * HH + f], t);
    }
}

__global__ void head_kernel(const float* __restrict__ W1, const float* __restrict__ b1,
                            const float* __restrict__ W2, const float* __restrict__ b2,
                            float* __restrict__ out) {
    __shared__ float z[NB * HH];
    int tid = threadIdx.x;
    const float invN = 1.f / (float)NN;
    for (int idx = tid; idx < NB * HH; idx += 256) {
        int b = idx >> 6, j = idx & 63;
        float acc = b1[j];
#pragma unroll
        for (int k = 0; k < HH; k++)
            acc = fmaf(g_pool[b * HH + k] * invN, W1[k * HH + j], acc);
        z[idx] = fmaxf(acc, 0.f);
    }
    __syncthreads();
    for (int idx = tid; idx < NB * NDOUT; idx += 256) {
        int b = idx >> 7, o = idx & 127;
        float acc = b2[o];
#pragma unroll
        for (int j = 0; j < HH; j++)
            acc = fmaf(z[b * HH + j], W2[j * NDOUT + o], acc);
        out[idx] = acc;
    }
}

// ---------------- GEMM1: y = W1^T @ [h ; agg], K=128, fp16, double-buffered -
__global__ __launch_bounds__(256) void mma_gemm1(const float* __restrict__ W,
                                                 const float* __restrict__ bias,
                                                 int hsel, int useOut) {
    extern __shared__ char smem[];
    float* bias_s = (float*)smem;
    uint4* Wp = (uint4*)(smem + 1024);                // [4 fq][8 ks16][32] = 16KB
    char* As = smem + 1024 + 16384;                   // 2 x (128 rows x RB)
    const uint32_t As_u = (uint32_t)__cvta_generic_to_shared(As);

    const int tid = threadIdx.x, lid = tid & 31, wid = tid >> 5;
    const int r = lid >> 2, cq = lid & 3;
    const int mq = wid & 1, nq = wid >> 1;
    const __half* hbase = hsel ? g_h2 : g_h;

    if (tid < 64) bias_s[tid] = bias[tid];
    for (int e = tid; e < 1024; e += 256) {
        int lane = e & 31, ks16 = (e >> 5) & 7, fq = e >> 8;
        int er = lane >> 2, ec = lane & 3;
        int m0 = fq * 16, k0 = ks16 * 16;
        uint4 w;
        w.x = f2h(W[(k0 + 2*ec)     * HH + m0 + er], W[(k0 + 2*ec + 1) * HH + m0 + er]);
        w.y = f2h(W[(k0 + 2*ec)     * HH + m0 + 8 + er], W[(k0 + 2*ec + 1) * HH + m0 + 8 + er]);
        w.z = f2h(W[(k0 + 2*ec + 8) * HH + m0 + er], W[(k0 + 2*ec + 9) * HH + m0 + er]);
        w.w = f2h(W[(k0 + 2*ec + 8) * HH + m0 + 8 + er], W[(k0 + 2*ec + 9) * HH + m0 + 8 + er]);
        Wp[e] = w;
    }

    auto issue_tile = [&](int t, int bufsel) {   // 4 commit groups
        int T = blockIdx.x * TPC + t;
        int b = T >> 8, n0 = (T & 255) << 7;
        uint32_t dst = As_u + bufsel * ABUF1;
        for (int c = 0; c < 4; c++) {
#pragma unroll
            for (int i = 0; i < 2; i++) {
                int idx = tid + i * 256;
                int k = c * 32 + (idx >> 4), n8 = idx & 15;
                const __half* src = ((k < HH) ? hbase : g_agg) +
                                    ((size_t)(b * HH + (k & 63))) * NN + n0 + n8 * 8;
                cpa16(dst + (uint32_t)(k * RB + n8 * 16), src);
            }
            cpcommit();
        }
    };

    float st[2][2] = {{0.f, 0.f}, {0.f, 0.f}};
    float sq[2][2] = {{0.f, 0.f}, {0.f, 0.f}};

    issue_tile(0, 0);
    issue_tile(1, 1);
    __syncthreads();   // bias_s/Wp fills visible before acc init

    for (int t = 0; t < TPC; t++) {
        int T = blockIdx.x * TPC + t;
        int b = T >> 8, n0 = (T & 255) << 7;
        uint32_t bufu = As_u + (t & 1) * ABUF1;

        float acc[2][4][4];
        {
            float b0 = bias_s[mq * 32 + r],       b1v = bias_s[mq * 32 + 8 + r];
            float b2v = bias_s[mq * 32 + 16 + r], b3 = bias_s[mq * 32 + 24 + r];
#pragma unroll
            for (int nt = 0; nt < 4; nt++) {
                acc[0][nt][0] = b0;  acc[0][nt][1] = b0;
                acc[0][nt][2] = b1v; acc[0][nt][3] = b1v;
                acc[1][nt][0] = b2v; acc[1][nt][1] = b2v;
                acc[1][nt][2] = b3;  acc[1][nt][3] = b3;
            }
        }

        int lastpend = (t + 1 < TPC) ? 4 : 0;   // groups of tile t+1 still in flight
        for (int c = 0; c < 4; c++) {
            cpwaitn(lastpend + 3 - c);
            __syncthreads();
#pragma unroll
            for (int j = 0; j < 2; j++) {
                int ks16 = c * 2 + j;
                uint4 A0 = Wp[((mq * 2 + 0) * 8 + ks16) * 32 + lid];
                uint4 A1 = Wp[((mq * 2 + 1) * 8 + ks16) * 32 + lid];
                uint32_t rowa = bufu + (uint32_t)((ks16 * 16 + (lid & 15)) * RB +
                                (nq * 32 + (lid >> 4) * 8) * 2);
                uint32_t b0, b1, b2, b3, b4, b5, b6, b7;
                LDMX4T(b0, b1, b2, b3, rowa);
                LDMX4T(b4, b5, b6, b7, rowa + 32);
                mma_f16(acc[0][0], A0, b0, b1); mma_f16(acc[1][0], A1, b0, b1);
                mma_f16(acc[0][1], A0, b2, b3); mma_f16(acc[1][1], A1, b2, b3);
                mma_f16(acc[0][2], A0, b4, b5); mma_f16(acc[1][2], A1, b4, b5);
                mma_f16(acc[0][3], A0, b6, b7); mma_f16(acc[1][3], A1, b6, b7);
            }
        }
        __syncthreads();   // all warps done reading bufu

        if (t + 2 < TPC) issue_tile(t + 2, t & 1);

#pragma unroll
        for (int f = 0; f < 2; f++) {
            size_t base0 = ((size_t)(b * HH + mq * 32 + f * 16 + r)) * NN + n0 + nq * 32;
            size_t base1 = base0 + (size_t)8 * NN;
#pragma unroll
            for (int nt = 0; nt < 4; nt++) {
                int nn = nt * 8 + 2 * cq;
                *(uint32_t*)(g_y + base0 + nn) = f2h(acc[f][nt][0], acc[f][nt][1]);
                *(uint32_t*)(g_y + base1 + nn) = f2h(acc[f][nt][2], acc[f][nt][3]);
                st[f][0] += acc[f][nt][0] + acc[f][nt][1];
                sq[f][0] += acc[f][nt][0] * acc[f][nt][0] + acc[f][nt][1] * acc[f][nt][1];
                st[f][1] += acc[f][nt][2] + acc[f][nt][3];
                sq[f][1] += acc[f][nt][2] * acc[f][nt][2] + acc[f][nt][3] * acc[f][nt][3];
            }
        }
    }

#pragma unroll
    for (int d = 1; d < 4; d <<= 1)
#pragma unroll
        for (int f = 0; f < 2; f++)
#pragma unroll
            for (int hv = 0; hv < 2; hv++) {
                st[f][hv] += __shfl_xor_sync(0xffffffffu, st[f][hv], d);
                sq[f][hv] += __shfl_xor_sync(0xffffffffu, sq[f][hv], d);
            }
    if (cq == 0)
#pragma unroll
        for (int f = 0; f < 2; f++) {
            int m = mq * 32 + f * 16 + r;
            atomicAdd(&g_stats[useOut][m], st[f][0]);
            atomicAdd(&g_stats[useOut][HH + m], sq[f][0]);
            atomicAdd(&g_stats[useOut][m + 8], st[f][1]);
            atomicAdd(&g_stats[useOut][HH + m + 8], sq[f][1]);
        }
}

// ---------------- GEMM2: y = W2^T @ relu(bn(y)), K=64, fp16, double-buffered
__global__ __launch_bounds__(256) void mma_gemm2(const float* __restrict__ W,
                                                 const float* __restrict__ bias,
                                                 const float* __restrict__ gamma,
                                                 const float* __restrict__ beta,
                                                 int useIn, int useOut) {
    extern __shared__ char smem[];
    float* bias_s = (float*)smem;
    float* sc_s   = (float*)(smem + 256);
    float* sh_s   = (float*)(smem + 512);
    uint4* Wp = (uint4*)(smem + 1024);                // [4 fq][4 ks16][32] = 8KB
    char* As = smem + 1024 + 8192;                    // 2 x (64 rows x RB)
    const uint32_t As_u = (uint32_t)__cvta_generic_to_shared(As);

    const int tid = threadIdx.x, lid = tid & 31, wid = tid >> 5;
    const int r = lid >> 2, cq = lid & 3;
    const int mq = wid & 1, nq = wid >> 1;

    if (tid < 64) bias_s[tid] = bias[tid];
    if (tid >= 64 && tid < 128) {
        float sc, sh;
        bn_coef(useIn, tid - 64, gamma, beta, sc, sh);
        sc_s[tid - 64] = sc; sh_s[tid - 64] = sh;
    }
    for (int e = tid; e < 512; e += 256) {
        int lane = e & 31, ks16 = (e >> 5) & 3, fq = e >> 7;
        int er = lane >> 2, ec = lane & 3;
        int m0 = fq * 16, k0 = ks16 * 16;
        uint4 w;
        w.x = f2h(W[(k0 + 2*ec)     * HH + m0 + er], W[(k0 + 2*ec + 1) * HH + m0 + er]);
        w.y = f2h(W[(k0 + 2*ec)     * HH + m0 + 8 + er], W[(k0 + 2*ec + 1) * HH + m0 + 8 + er]);
        w.z = f2h(W[(k0 + 2*ec + 8) * HH + m0 + er], W[(k0 + 2*ec + 9) * HH + m0 + er]);
        w.w = f2h(W[(k0 + 2*ec + 8) * HH + m0 + 8 + er], W[(k0 + 2*ec + 9) * HH + m0 + 8 + er]);
        Wp[e] = w;
    }

    float st[2][2] = {{0.f, 0.f}, {0.f, 0.f}};
    float sq[2][2] = {{0.f, 0.f}, {0.f, 0.f}};

    uint4 cur[4], nxt[4];
    auto loadc = [&](int t, uint4* pf) {    // whole 64xK tile, 4 uint4/thread
        int T = blockIdx.x * TPC + t;
        int b = T >> 8, n0 = (T & 255) << 7;
#pragma unroll
        for (int i = 0; i < 4; i++) {
            int idx = tid + i * 256;
            int k = idx >> 4, n8 = idx & 15;
            pf[i] = *(const uint4*)(g_y + ((size_t)(b * HH + k)) * NN + n0 + n8 * 8);
        }
    };
    auto stsc = [&](uint32_t bufu, const uint4* pf) {
#pragma unroll
        for (int i = 0; i < 4; i++) {
            int idx = tid + i * 256;
            int k = idx >> 4, n8 = idx & 15;
            float sc = sc_s[k], sh = sh_s[k];
            float v[8];
            u4tof8(pf[i], v);
#pragma unroll
            for (int j = 0; j < 8; j++) v[j] = fmaxf(fmaf(v[j], sc, sh), 0.f);
            uint4 o = f8tou4(v);
            asm volatile("st.shared.v4.b32 [%0], {%1,%2,%3,%4};"
                :: "r"(bufu + (uint32_t)(k * RB + n8 * 16)),
                   "r"(o.x), "r"(o.y), "r"(o.z), "r"(o.w) : "memory");
        }
    };

    loadc(0, cur);
    __syncthreads();   // bias_s/sc_s/sh_s/Wp ready

    for (int t = 0; t < TPC; t++) {
        int T = blockIdx.x * TPC + t;
        int b = T >> 8, n0 = (T & 255) << 7;
        uint32_t bufu = As_u + (t & 1) * ABUF2;

        stsc(bufu, cur);
        __syncthreads();            // tile visible; also fences MMA(t-1) readers

        if (t + 1 < TPC) loadc(t + 1, nxt);   // LDGs land during MMAs below

        float acc[2][4][4];
        {
            float b0 = bias_s[mq * 32 + r],       b1v = bias_s[mq * 32 + 8 + r];
            float b2v = bias_s[mq * 32 + 16 + r], b3 = bias_s[mq * 32 + 24 + r];
#pragma unroll
            for (int nt = 0; nt < 4; nt++) {
                acc[0][nt][0] = b0;  acc[0][nt][1] = b0;
                acc[0][nt][2] = b1v; acc[0][nt][3] = b1v;
                acc[1][nt][0] = b2v; acc[1][nt][1] = b2v;
                acc[1][nt][2] = b3;  acc[1][nt][3] = b3;
            }
        }

#pragma unroll
        for (int ks16 = 0; ks16 < 4; ks16++) {
            uint4 A0 = Wp[((mq * 2 + 0) * 4 + ks16) * 32 + lid];
            uint4 A1 = Wp[((mq * 2 + 1) * 4 + ks16) * 32 + lid];
            uint32_t rowa = bufu + (uint32_t)((ks16 * 16 + (lid & 15)) * RB +
                            (nq * 32 + (lid >> 4) * 8) * 2);
            uint32_t b0, b1, b2, b3, b4, b5, b6, b7;
            LDMX4T(b0, b1, b2, b3, rowa);
            LDMX4T(b4, b5, b6, b7, rowa + 32);
            mma_f16(acc[0][0], A0, b0, b1); mma_f16(acc[1][0], A1, b0, b1);
            mma_f16(acc[0][1], A0, b2, b3); mma_f16(acc[1][1], A1, b2, b3);
            mma_f16(acc[0][2], A0, b4, b5); mma_f16(acc[1][2], A1, b4, b5);
            mma_f16(acc[0][3], A0, b6, b7); mma_f16(acc[1][3], A1, b6, b7);
        }

#pragma unroll
        for (int f = 0; f < 2; f++) {
            size_t base0 = ((size_t)(b * HH + mq * 32 + f * 16 + r)) * NN + n0 + nq * 32;
            size_t base1 = base0 + (size_t)8 * NN;
#pragma unroll
            for (int nt = 0; nt < 4; nt++) {
                int nn = nt * 8 + 2 * cq;
                *(uint32_t*)(g_y + base0 + nn) = f2h(acc[f][nt][0], acc[f][nt][1]);
                *(uint32_t*)(g_y + base1 + nn) = f2h(acc[f][nt][2], acc[f][nt][3]);
                st[f][0] += acc[f][nt][0] + acc[f][nt][1];
                sq[f][0] += acc[f][nt][0] * acc[f][nt][0] + acc[f][nt][1] * acc[f][nt][1];
                st[f][1] += acc[f][nt][2] + acc[f][nt][3];
                sq[f][1] += acc[f][nt][2] * acc[f][nt][2] + acc[f][nt][3] * acc[f][nt][3];
            }
        }
#pragma unroll
        for (int i = 0; i < 4; i++) cur[i] = nxt[i];
    }

#pragma unroll
    for (int d = 1; d < 4; d <<= 1)
#pragma unroll
        for (int f = 0; f < 2; f++)
#pragma unroll
            for (int hv = 0; hv < 2; hv++) {
                st[f][hv] += __shfl_xor_sync(0xffffffffu, st[f][hv], d);
                sq[f][hv] += __shfl_xor_sync(0xffffffffu, sq[f][hv], d);
            }
    if (cq == 0)
#pragma unroll
        for (int f = 0; f < 2; f++) {
            int m = mq * 32 + f * 16 + r;
            atomicAdd(&g_stats[useOut][m], st[f][0]);
            atomicAdd(&g_stats[useOut][HH + m], sq[f][0]);
            atomicAdd(&g_stats[useOut][m + 8], st[f][1]);
            atomicAdd(&g_stats[useOut][HH + m + 8], sq[f][1]);
        }
}

// ---------------- driver ---------------------------------------------------
extern "C" void kernel_launch(void* const* d_in, const int* in_sizes, int n_in,
                              void* d_out, int out_size) {
    const float* x    = (const float*)d_in[0];
    const float* embW = (const float*)d_in[2];
    const float* embB = (const float*)d_in[3];
    const float* W1   = (const float*)d_in[4];
    const float* b1   = (const float*)d_in[5];
    const float* g1   = (const float*)d_in[6];
    const float* be1  = (const float*)d_in[7];
    const float* W2   = (const float*)d_in[8];
    const float* b2   = (const float*)d_in[9];
    const float* g2   = (const float*)d_in[10];
    const float* be2  = (const float*)d_in[11];
    const float* hW1  = (const float*)d_in[12];
    const float* hb1  = (const float*)d_in[13];
    const float* hW2  = (const float*)d_in[14];
    const float* hb2  = (const float*)d_in[15];
    float* out = (float*)d_out;

    const int SMEM_G1 = 1024 + 16384 + 2 * ABUF1;  // 87040
    const int SMEM_G2 = 1024 + 8192 + 2 * ABUF2;   // 44032
    cudaFuncSetAttribute(mma_gemm1, cudaFuncAttributeMaxDynamicSharedMemorySize, SMEM_G1);
    cudaFuncSetAttribute(mma_gemm2, cudaFuncAttributeMaxDynamicSharedMemorySize, SMEM_G2);

    const int GRID = MROWS / 128 / TPC;  // 1024

    zero_kernel<<<1, 256>>>();
    embed_agg_kernel<<<dim3(16, HH, NB), 256>>>(x, embW, embB);
    for (int l = 0; l < 3; l++) {
        int hsel = l & 1;  // l0: g_h, l1: g_h2, l2: g_h
        mma_gemm1<<<GRID, 256, SMEM_G1>>>(W1 + l * 2 * HH * HH, b1 + l * HH, hsel, l * 2);
        mma_gemm2<<<GRID, 256, SMEM_G2>>>(W2 + l * HH * HH, b2 + l * HH,
                                          g1 + l * HH, be1 + l * HH, l * 2, l * 2 + 1);
        if (l < 2)
            fused_res_agg<<<dim3(4, HH, NB), 256>>>(hsel, g2 + l * HH, be2 + l * HH,
                                                    l * 2 + 1);
        else
            relu_pool<<<dim3(4, HH, NB), 256>>>(hsel, g2 + l * HH, be2 + l * HH,
                                                l * 2 + 1);
    }
    head_kernel<<<1, 256>>>(hW1, hb1, hW2, hb2, out);
}

// round 15
// speedup vs baseline: 1.0273x; 1.0273x over previous
#include <cuda_runtime.h>
#include <cuda_fp16.h>
#include <cstdint>

#define NB 16
#define NN 32768          // nodes = 128*256 torus
#define HH 64
#define NDOUT 128
#define MROWS (NB*NN)     // 524288
#define EPSBN 1e-5f
#define RB 272            // As row bytes: 256 data + 16 pad -> conflict-free ldmatrix
#define TPC 4

// ---------------- scratch (feature-major layout: [b][f][n]) ----------------
__device__ __half g_h[NB*HH*NN];     // trunk ping
__device__ __half g_h2[NB*HH*NN];    // trunk pong
__device__ __half g_agg[NB*HH*NN];   // stencil aggregate (gemm1 input)
__device__ __half g_y[NB*HH*NN];     // gemm outputs (pre-BN), fp16; stats from fp32 accs
__device__ float  g_stats[6][2*HH];
__device__ float  g_pool[NB*HH];

// ---------------- helpers ---------------------------------------------------
__device__ __forceinline__ float2 h2f(uint32_t u) {
    __half2 h = *(__half2*)&u;
    return __half22float2(h);
}
__device__ __forceinline__ uint32_t f2h(float a, float b) {
    __half2 h = __floats2half2_rn(a, b);
    return *(uint32_t*)&h;
}
__device__ __forceinline__ void u4tof8(uint4 u, float* f) {
    float2 a = h2f(u.x), b = h2f(u.y), c = h2f(u.z), d = h2f(u.w);
    f[0] = a.x; f[1] = a.y; f[2] = b.x; f[3] = b.y;
    f[4] = c.x; f[5] = c.y; f[6] = d.x; f[7] = d.y;
}
__device__ __forceinline__ uint4 f8tou4(const float* f) {
    uint4 u;
    u.x = f2h(f[0], f[1]); u.y = f2h(f[2], f[3]);
    u.z = f2h(f[4], f[5]); u.w = f2h(f[6], f[7]);
    return u;
}
__device__ __forceinline__ void mma_f16(float* d, const uint4& a, uint32_t b0, uint32_t b1) {
    asm volatile(
        "mma.sync.aligned.m16n8k16.row.col.f32.f16.f16.f32 "
        "{%0,%1,%2,%3}, {%4,%5,%6,%7}, {%8,%9}, {%0,%1,%2,%3};"
        : "+f"(d[0]), "+f"(d[1]), "+f"(d[2]), "+f"(d[3])
        : "r"(a.x), "r"(a.y), "r"(a.z), "r"(a.w), "r"(b0), "r"(b1));
}
#define LDMX4T(r0, r1, r2, r3, addr) \
    asm volatile("ldmatrix.sync.aligned.m8n8.x4.trans.shared.b16 {%0,%1,%2,%3}, [%4];" \
        : "=r"(r0), "=r"(r1), "=r"(r2), "=r"(r3) : "r"(addr))
__device__ __forceinline__ void bn_coef(int use, int f, const float* g, const float* be,
                                        float& sc, float& sh) {
    const float invM = 1.f / (float)MROWS;
    float s = g_stats[use][f], q = g_stats[use][HH + f];
    float m = s * invM;
    float v = q * invM - m * m;
    float r = rsqrtf(v + EPSBN);
    sc = g[f] * r;
    sh = fmaf(-m, sc, be[f]);
}
__device__ __forceinline__ void cpa16(uint32_t dst, const void* src) {
    asm volatile("cp.async.cg.shared.global [%0], [%1], 16;" :: "r"(dst), "l"(src));
}
__device__ __forceinline__ void cpcommit() { asm volatile("cp.async.commit_group;"); }
__device__ __forceinline__ void cpwait(int n) {
    switch (n) {
        case 0: asm volatile("cp.async.wait_group 0;"); break;
        case 1: asm volatile("cp.async.wait_group 1;"); break;
        case 2: asm volatile("cp.async.wait_group 2;"); break;
        default: asm volatile("cp.async.wait_group 3;"); break;
    }
}

// ---------------- small kernels ---------------------------------------------
__global__ void zero_kernel() {
    int tid = threadIdx.x;
    float* s = &g_stats[0][0];
    for (int i = tid; i < 6 * 2 * HH; i += 256) s[i] = 0.f;
    for (int i = tid; i < NB * HH; i += 256) g_pool[i] = 0.f;
}

// fused embedding + initial stencil: h = relu(emb(x)); agg = 0.25*sum(nbrs(h))
// halo h values recomputed from x (x per-batch is 393KB -> L2-resident)
__global__ void embed_agg_kernel(const float* __restrict__ x,
                                 const float* __restrict__ W,
                                 const float* __restrict__ bias) {
    int b = blockIdx.z, f = blockIdx.y;
    float w0 = W[f], w1 = W[HH + f], w2 = W[2 * HH + f], bb = bias[f];
    int n = blockIdx.x * 2048 + threadIdx.x * 8;
    const float* xb = x + (size_t)(b * 3) * NN;

    auto emb1 = [&](int idx) {
        return fmaxf(fmaf(xb[idx], w0, fmaf(xb[NN + idx], w1,
                     fmaf(xb[2 * NN + idx], w2, bb))), 0.f);
    };
    auto emb8 = [&](int idx, float* r) {
#pragma unroll
        for (int h = 0; h < 2; h++) {
            float4 a = *(const float4*)(xb + idx + h * 4);
            float4 c = *(const float4*)(xb + NN + idx + h * 4);
            float4 d = *(const float4*)(xb + 2 * NN + idx + h * 4);
            r[h*4+0] = fmaxf(fmaf(a.x, w0, fmaf(c.x, w1, fmaf(d.x, w2, bb))), 0.f);
            r[h*4+1] = fmaxf(fmaf(a.y, w0, fmaf(c.y, w1, fmaf(d.y, w2, bb))), 0.f);
            r[h*4+2] = fmaxf(fmaf(a.z, w0, fmaf(c.z, w1, fmaf(d.z, w2, bb))), 0.f);
            r[h*4+3] = fmaxf(fmaf(a.w, w0, fmaf(c.w, w1, fmaf(d.w, w2, bb))), 0.f);
        }
    };

    float c[8], u[8], d[8], o[8];
    emb8(n, c);
    emb8((n + 256) & 32767, u);
    emb8((n - 256) & 32767, d);
    int base = n & ~255, z0 = n & 255;
    float lf = emb1(base | ((z0 - 1) & 255));
    float rt = emb1(base | ((z0 + 8) & 255));
#pragma unroll
    for (int j = 0; j < 8; j++) {
        float L = (j == 0) ? lf : c[j - 1];
        float R = (j == 7) ? rt : c[j + 1];
        o[j] = 0.25f * (u[j] + d[j] + L + R);
    }
    size_t plane = (size_t)(b * HH + f) * NN;
    *(uint4*)(g_h + plane + n) = f8tou4(c);
    *(uint4*)(g_agg + plane + n) = f8tou4(o);
}

// ---------------- fused: h_out = h_in + relu(bn(y)); agg = stencil(h_out) ---
__global__ __launch_bounds__(256) void fused_res_agg(int hselIn,
                                                     const float* __restrict__ gamma,
                                                     const float* __restrict__ beta,
                                                     int use) {
    __shared__ float hb[8704];
    __shared__ float ss[2];
    int b = blockIdx.z, f = blockIdx.y, tid = threadIdx.x;
    if (tid == 0) {
        float sc, sh;
        bn_coef(use, f, gamma, beta, sc, sh);
        ss[0] = sc; ss[1] = sh;
    }
    __syncthreads();
    float sc = ss[0], sh = ss[1];
    const __half* hin = hselIn ? g_h2 : g_h;
    __half* hout = hselIn ? g_h : g_h2;
    size_t plane = (size_t)(b * HH + f) * NN;
    int n0 = blockIdx.x * 8192;

    for (int q8 = tid; q8 < 1088; q8 += 256) {
        int nh = (n0 - 256 + q8 * 8) & 32767;
        float hf[8], yf[8];
        u4tof8(*(const uint4*)(hin + plane + nh), hf);
        u4tof8(*(const uint4*)(g_y + plane + nh), yf);
#pragma unroll
        for (int j = 0; j < 8; j++) hf[j] += fmaxf(fmaf(yf[j], sc, sh), 0.f);
        *(float4*)&hb[q8 * 8] = make_float4(hf[0], hf[1], hf[2], hf[3]);
        *(float4*)&hb[q8 * 8 + 4] = make_float4(hf[4], hf[5], hf[6], hf[7]);
        if (q8 >= 32 && q8 < 1056) *(uint4*)(hout + plane + nh) = f8tou4(hf);
    }
    __syncthreads();
    for (int q8 = tid; q8 < 1024; q8 += 256) {
        int i = 256 + q8 * 8;
        int n = n0 + q8 * 8;
        float o[8];
#pragma unroll
        for (int j = 0; j < 8; j++) {
            int zj = (n + j) & 255;
            int rowbase = i + j - zj;
            float lf = hb[rowbase + ((zj + 255) & 255)];
            float rt = hb[rowbase + ((zj + 1) & 255)];
            o[j] = 0.25f * (hb[i + j - 256] + hb[i + j + 256] + lf + rt);
        }
        *(uint4*)(g_agg + plane + n) = f8tou4(o);
    }
}

// ---------------- final layer: pool(h_in + relu(bn(y))), no h write ---------
__global__ __launch_bounds__(256) void relu_pool(int hselIn,
                                                 const float* __restrict__ gamma,
                                                 const float* __restrict__ beta,
                                                 int use) {
    __shared__ float ss[2];
    __shared__ float wsum[8];
    int b = blockIdx.z, f = blockIdx.y, tid = threadIdx.x;
    if (tid == 0) {
        float sc, sh;
        bn_coef(use, f, gamma, beta, sc, sh);
        ss[0] = sc; ss[1] = sh;
    }
    __syncthreads();
    float sc = ss[0], sh = ss[1];
    const __half* hin = hselIn ? g_h2 : g_h;
    size_t plane = (size_t)(b * HH + f) * NN;
    int n0 = blockIdx.x * 8192;
    float ps = 0.f;
    for (int q8 = tid; q8 < 1024; q8 += 256) {
        int n = n0 + q8 * 8;
        float hf[8], yf[8];
        u4tof8(*(const uint4*)(hin + plane + n), hf);
        u4tof8(*(const uint4*)(g_y + plane + n), yf);
#pragma unroll
        for (int j = 0; j < 8; j++) ps += hf[j] + fmaxf(fmaf(yf[j], sc, sh), 0.f);
    }
#pragma unroll
    for (int off = 16; off; off >>= 1) ps += __shfl_down_sync(0xffffffffu, ps, off);
    if ((tid & 31) == 0) wsum[tid >> 5] = ps;
    __syncthreads();
    if (tid == 0) {
        float t = 0.f;
#pragma unroll
        for (int w = 0; w < 8; w++) t += wsum[w];
        atomicAdd(&g_pool[b * HH + f], t);
    }
}

__global__ void head_kernel(const float* __restrict__ W1, const float* __restrict__ b1,
                            const float* __restrict__ W2, const float* __restrict__ b2,
                            float* __restrict__ out) {
    __shared__ float z[NB * HH];
    int tid = threadIdx.x;
    const float invN = 1.f / (float)NN;
    for (int idx = tid; idx < NB * HH; idx += 256) {
        int b = idx >> 6, j = idx & 63;
        float acc = b1[j];
#pragma unroll
        for (int k = 0; k < HH; k++)
            acc = fmaf(g_pool[b * HH + k] * invN, W1[k * HH + j], acc);
        z[idx] = fmaxf(acc, 0.f);
    }
    __syncthreads();
    for (int idx = tid; idx < NB * NDOUT; idx += 256) {
        int b = idx >> 7, o = idx & 127;
        float acc = b2[o];
#pragma unroll
        for (int j = 0; j < HH; j++)
            acc = fmaf(z[b * HH + j], W2[j * NDOUT + o], acc);
        out[idx] = acc;
    }
}

// ---------------- GEMM1: y = W1^T @ [h ; agg], K=128, fp16, cp.async --------
// (verified R13 version: single-buffered, 3 CTAs/SM)
__global__ __launch_bounds__(256) void mma_gemm1(const float* __restrict__ W,
                                                 const float* __restrict__ bias,
                                                 int hsel, int useOut) {
    extern __shared__ char smem[];
    float* bias_s = (float*)smem;
    uint4* Wp = (uint4*)(smem + 1024);                // [4 fq][8 ks16][32] = 16KB
    char* As = smem + 1024 + 16384;                   // 128 rows x RB
    const uint32_t As_u = (uint32_t)__cvta_generic_to_shared(As);

    const int tid = threadIdx.x, lid = tid & 31, wid = tid >> 5;
    const int r = lid >> 2, cq = lid & 3;
    const int mq = wid & 1, nq = wid >> 1;
    const __half* hbase = hsel ? g_h2 : g_h;

    if (tid < 64) bias_s[tid] = bias[tid];
    for (int e = tid; e < 1024; e += 256) {
        int lane = e & 31, ks16 = (e >> 5) & 7, fq = e >> 8;
        int er = lane >> 2, ec = lane & 3;
        int m0 = fq * 16, k0 = ks16 * 16;
        uint4 w;
        w.x = f2h(W[(k0 + 2*ec)     * HH + m0 + er], W[(k0 + 2*ec + 1) * HH + m0 + er]);
        w.y = f2h(W[(k0 + 2*ec)     * HH + m0 + 8 + er], W[(k0 + 2*ec + 1) * HH + m0 + 8 + er]);
        w.z = f2h(W[(k0 + 2*ec + 8) * HH + m0 + er], W[(k0 + 2*ec + 9) * HH + m0 + er]);
        w.w = f2h(W[(k0 + 2*ec + 8) * HH + m0 + 8 + er], W[(k0 + 2*ec + 9) * HH + m0 + 8 + er]);
        Wp[e] = w;
    }

    float st[2][2] = {{0.f, 0.f}, {0.f, 0.f}};
    float sq[2][2] = {{0.f, 0.f}, {0.f, 0.f}};

    // prologue: issue all 4 chunks of tile 0
    {
        int T = blockIdx.x * TPC;
        int b = T >> 8, n0 = (T & 255) << 7;
        for (int c = 0; c < 4; c++) {
#pragma unroll
            for (int i = 0; i < 2; i++) {
                int idx = tid + i * 256;
                int k = c * 32 + (idx >> 4), n8 = idx & 15;
                const __half* src = ((k < HH) ? hbase : g_agg) +
                                    ((size_t)(b * HH + (k & 63))) * NN + n0 + n8 * 8;
                cpa16(As_u + (uint32_t)(k * RB + n8 * 16), src);
            }
            cpcommit();
        }
    }
    __syncthreads();   // bias_s/Wp fills visible before acc init

    for (int t = 0; t < TPC; t++) {
        int T = blockIdx.x * TPC + t;
        int b = T >> 8, n0 = (T & 255) << 7;

        float acc[2][4][4];
        {
            float b0 = bias_s[mq * 32 + r],       b1v = bias_s[mq * 32 + 8 + r];
            float b2v = bias_s[mq * 32 + 16 + r], b3 = bias_s[mq * 32 + 24 + r];
#pragma unroll
            for (int nt = 0; nt < 4; nt++) {
                acc[0][nt][0] = b0;  acc[0][nt][1] = b0;
                acc[0][nt][2] = b1v; acc[0][nt][3] = b1v;
                acc[1][nt][0] = b2v; acc[1][nt][1] = b2v;
                acc[1][nt][2] = b3;  acc[1][nt][3] = b3;
            }
        }

        for (int c = 0; c < 4; c++) {
            cpwait(3 - c);
            __syncthreads();
#pragma unroll
            for (int j = 0; j < 2; j++) {
                int ks16 = c * 2 + j;
                uint4 A0 = Wp[((mq * 2 + 0) * 8 + ks16) * 32 + lid];
                uint4 A1 = Wp[((mq * 2 + 1) * 8 + ks16) * 32 + lid];
                uint32_t rowa = As_u + (uint32_t)((ks16 * 16 + (lid & 15)) * RB +
                                (nq * 32 + (lid >> 4) * 8) * 2);
                uint32_t b0, b1, b2, b3, b4, b5, b6, b7;
                LDMX4T(b0, b1, b2, b3, rowa);
                LDMX4T(b4, b5, b6, b7, rowa + 32);
                mma_f16(acc[0][0], A0, b0, b1); mma_f16(acc[1][0], A1, b0, b1);
                mma_f16(acc[0][1], A0, b2, b3); mma_f16(acc[1][1], A1, b2, b3);
                mma_f16(acc[0][2], A0, b4, b5); mma_f16(acc[1][2], A1, b4, b5);
                mma_f16(acc[0][3], A0, b6, b7); mma_f16(acc[1][3], A1, b6, b7);
            }
        }
        __syncthreads();

        if (t + 1 < TPC) {
            int T2 = T + 1;
            int b2 = T2 >> 8, n02 = (T2 & 255) << 7;
            for (int c = 0; c < 4; c++) {
#pragma unroll
                for (int i = 0; i < 2; i++) {
                    int idx = tid + i * 256;
                    int k = c * 32 + (idx >> 4), n8 = idx & 15;
                    const __half* src = ((k < HH) ? hbase : g_agg) +
                                        ((size_t)(b2 * HH + (k & 63))) * NN + n02 + n8 * 8;
                    cpa16(As_u + (uint32_t)(k * RB + n8 * 16), src);
                }
                cpcommit();
            }
        }

#pragma unroll
        for (int f = 0; f < 2; f++) {
            size_t base0 = ((size_t)(b * HH + mq * 32 + f * 16 + r)) * NN + n0 + nq * 32;
            size_t base1 = base0 + (size_t)8 * NN;
#pragma unroll
            for (int nt = 0; nt < 4; nt++) {
                int nn = nt * 8 + 2 * cq;
                *(uint32_t*)(g_y + base0 + nn) = f2h(acc[f][nt][0], acc[f][nt][1]);
                *(uint32_t*)(g_y + base1 + nn) = f2h(acc[f][nt][2], acc[f][nt][3]);
                st[f][0] += acc[f][nt][0] + acc[f][nt][1];
                sq[f][0] += acc[f][nt][0] * acc[f][nt][0] + acc[f][nt][1] * acc[f][nt][1];
                st[f][1] += acc[f][nt][2] + acc[f][nt][3];
                sq[f][1] += acc[f][nt][2] * acc[f][nt][2] + acc[f][nt][3] * acc[f][nt][3];
            }
        }
    }

#pragma unroll
    for (int d = 1; d < 4; d <<= 1)
#pragma unroll
        for (int f = 0; f < 2; f++)
#pragma unroll
            for (int hv = 0; hv < 2; hv++) {
                st[f][hv] += __shfl_xor_sync(0xffffffffu, st[f][hv], d);
                sq[f][hv] += __shfl_xor_sync(0xffffffffu, sq[f][hv], d);
            }
    if (cq == 0)
#pragma unroll
        for (int f = 0; f < 2; f++) {
            int m = mq * 32 + f * 16 + r;
            atomicAdd(&g_stats[useOut][m], st[f][0]);
            atomicAdd(&g_stats[useOut][HH + m], sq[f][0]);
            atomicAdd(&g_stats[useOut][m + 8], st[f][1]);
            atomicAdd(&g_stats[useOut][HH + m + 8], sq[f][1]);
        }
}

// ---------------- GEMM2: y = W2^T @ relu(bn(y)), K=64, fp16, reg-pipelined --
// (verified R13 version)
__global__ __launch_bounds__(256) void mma_gemm2(const float* __restrict__ W,
                                                 const float* __restrict__ bias,
                                                 const float* __restrict__ gamma,
                                                 const float* __restrict__ beta,
                                                 int useIn, int useOut) {
    extern __shared__ char smem[];
    float* bias_s = (float*)smem;
    float* sc_s   = (float*)(smem + 256);
    float* sh_s   = (float*)(smem + 512);
    uint4* Wp = (uint4*)(smem + 1024);                // [4 fq][4 ks16][32] = 8KB
    char* As = smem + 1024 + 8192;                    // 64 rows x RB

    const int tid = threadIdx.x, lid = tid & 31, wid = tid >> 5;
    const int r = lid >> 2, cq = lid & 3;
    const int mq = wid & 1, nq = wid >> 1;
    const uint32_t As_u = (uint32_t)__cvta_generic_to_shared(As);

    if (tid < 64) bias_s[tid] = bias[tid];
    if (tid >= 64 && tid < 128) {
        float sc, sh;
        bn_coef(useIn, tid - 64, gamma, beta, sc, sh);
        sc_s[tid - 64] = sc; sh_s[tid - 64] = sh;
    }
    for (int e = tid; e < 512; e += 256) {
        int lane = e & 31, ks16 = (e >> 5) & 3, fq = e >> 7;
        int er = lane >> 2, ec = lane & 3;
        int m0 = fq * 16, k0 = ks16 * 16;
        uint4 w;
        w.x = f2h(W[(k0 + 2*ec)     * HH + m0 + er], W[(k0 + 2*ec + 1) * HH + m0 + er]);
        w.y = f2h(W[(k0 + 2*ec)     * HH + m0 + 8 + er], W[(k0 + 2*ec + 1) * HH + m0 + 8 + er]);
        w.z = f2h(W[(k0 + 2*ec + 8) * HH + m0 + er], W[(k0 + 2*ec + 9) * HH + m0 + er]);
        w.w = f2h(W[(k0 + 2*ec + 8) * HH + m0 + 8 + er], W[(k0 + 2*ec + 9) * HH + m0 + 8 + er]);
        Wp[e] = w;
    }
    __syncthreads();   // bias_s/sc_s/sh_s/Wp ready

    float st[2][2] = {{0.f, 0.f}, {0.f, 0.f}};
    float sq[2][2] = {{0.f, 0.f}, {0.f, 0.f}};

    uint4 pfA[2], pfB[2];
    auto loadc = [&](int t, int c, uint4* pf) {
        int T = blockIdx.x * TPC + t;
        int b = T >> 8, n0 = (T & 255) << 7;
#pragma unroll
        for (int i = 0; i < 2; i++) {
            int idx = tid + i * 256;
            int k = c * 32 + (idx >> 4), n8 = idx & 15;
            pf[i] = *(const uint4*)(g_y + ((size_t)(b * HH + k)) * NN + n0 + n8 * 8);
        }
    };
    auto stsc = [&](int c, const uint4* pf) {
#pragma unroll
        for (int i = 0; i < 2; i++) {
            int idx = tid + i * 256;
            int k = c * 32 + (idx >> 4), n8 = idx & 15;
            float sc = sc_s[k], sh = sh_s[k];
            float v[8];
            u4tof8(pf[i], v);
#pragma unroll
            for (int j = 0; j < 8; j++) v[j] = fmaxf(fmaf(v[j], sc, sh), 0.f);
            *(uint4*)(As + k * RB + n8 * 16) = f8tou4(v);
        }
    };
    auto mmachunk = [&](int c, float acc[2][4][4]) {
#pragma unroll
        for (int j = 0; j < 2; j++) {
            int ks16 = c * 2 + j;
            uint4 A0 = Wp[((mq * 2 + 0) * 4 + ks16) * 32 + lid];
            uint4 A1 = Wp[((mq * 2 + 1) * 4 + ks16) * 32 + lid];
            uint32_t rowa = As_u + (uint32_t)((ks16 * 16 + (lid & 15)) * RB +
                            (nq * 32 + (lid >> 4) * 8) * 2);
            uint32_t b0, b1, b2, b3, b4, b5, b6, b7;
            LDMX4T(b0, b1, b2, b3, rowa);
            LDMX4T(b4, b5, b6, b7, rowa + 32);
            mma_f16(acc[0][0], A0, b0, b1); mma_f16(acc[1][0], A1, b0, b1);
            mma_f16(acc[0][1], A0, b2, b3); mma_f16(acc[1][1], A1, b2, b3);
            mma_f16(acc[0][2], A0, b4, b5); mma_f16(acc[1][2], A1, b4, b5);
            mma_f16(acc[0][3], A0, b6, b7); mma_f16(acc[1][3], A1, b6, b7);
        }
    };

    loadc(0, 0, pfA);
    for (int t = 0; t < TPC; t++) {
        int T = blockIdx.x * TPC + t;
        int b = T >> 8, n0 = (T & 255) << 7;

        stsc(0, pfA);
        loadc(t, 1, pfB);
        __syncthreads();            // chunk 0 visible

        float acc[2][4][4];
        {
            float b0 = bias_s[mq * 32 + r],       b1v = bias_s[mq * 32 + 8 + r];
            float b2v = bias_s[mq * 32 + 16 + r], b3 = bias_s[mq * 32 + 24 + r];
#pragma unroll
            for (int nt = 0; nt < 4; nt++) {
                acc[0][nt][0] = b0;  acc[0][nt][1] = b0;
                acc[0][nt][2] = b1v; acc[0][nt][3] = b1v;
                acc[1][nt][0] = b2v; acc[1][nt][1] = b2v;
                acc[1][nt][2] = b3;  acc[1][nt][3] = b3;
            }
        }

        mmachunk(0, acc);
        stsc(1, pfB);               // disjoint region: safe during chunk-0 MMAs
        if (t + 1 < TPC) loadc(t + 1, 0, pfA);
        __syncthreads();            // chunk 1 visible + chunk-0 reads done
        mmachunk(1, acc);

#pragma unroll
        for (int f = 0; f < 2; f++) {
            size_t base0 = ((size_t)(b * HH + mq * 32 + f * 16 + r)) * NN + n0 + nq * 32;
            size_t base1 = base0 + (size_t)8 * NN;
#pragma unroll
            for (int nt = 0; nt < 4; nt++) {
                int nn = nt * 8 + 2 * cq;
                *(uint32_t*)(g_y + base0 + nn) = f2h(acc[f][nt][0], acc[f][nt][1]);
                *(uint32_t*)(g_y + base1 + nn) = f2h(acc[f][nt][2], acc[f][nt][3]);
                st[f][0] += acc[f][nt][0] + acc[f][nt][1];
                sq[f][0] += acc[f][nt][0] * acc[f][nt][0] + acc[f][nt][1] * acc[f][nt][1];
                st[f][1] += acc[f][nt][2] + acc[f][nt][3];
                sq[f][1] += acc[f][nt][2] * acc[f][nt][2] + acc[f][nt][3] * acc[f][nt][3];
            }
        }
        __syncthreads();            // As reads done before next tile's STS
    }

#pragma unroll
    for (int d = 1; d < 4; d <<= 1)
#pragma unroll
        for (int f = 0; f < 2; f++)
#pragma unroll
            for (int hv = 0; hv < 2; hv++) {
                st[f][hv] += __shfl_xor_sync(0xffffffffu, st[f][hv], d);
                sq[f][hv] += __shfl_xor_sync(0xffffffffu, sq[f][hv], d);
            }
    if (cq == 0)
#pragma unroll
        for (int f = 0; f < 2; f++) {
            int m = mq * 32 + f * 16 + r;
            atomicAdd(&g_stats[useOut][m], st[f][0]);
            atomicAdd(&g_stats[useOut][HH + m], sq[f][0]);
            atomicAdd(&g_stats[useOut][m + 8], st[f][1]);
            atomicAdd(&g_stats[useOut][HH + m + 8], sq[f][1]);
        }
}

// ---------------- driver ---------------------------------------------------
extern "C" void kernel_launch(void* const* d_in, const int* in_sizes, int n_in,
                              void* d_out, int out_size) {
    const float* x    = (const float*)d_in[0];
    const float* embW = (const float*)d_in[2];
    const float* embB = (const float*)d_in[3];
    const float* W1   = (const float*)d_in[4];
    const float* b1   = (const float*)d_in[5];
    const float* g1   = (const float*)d_in[6];
    const float* be1  = (const float*)d_in[7];
    const float* W2   = (const float*)d_in[8];
    const float* b2   = (const float*)d_in[9];
    const float* g2   = (const float*)d_in[10];
    const float* be2  = (const float*)d_in[11];
    const float* hW1  = (const float*)d_in[12];
    const float* hb1  = (const float*)d_in[13];
    const float* hW2  = (const float*)d_in[14];
    const float* hb2  = (const float*)d_in[15];
    float* out = (float*)d_out;

    const int SMEM_G1 = 1024 + 16384 + 128 * RB;  // 52224
    const int SMEM_G2 = 1024 + 8192 + 64 * RB;    // 26624
    cudaFuncSetAttribute(mma_gemm1, cudaFuncAttributeMaxDynamicSharedMemorySize, SMEM_G1);
    cudaFuncSetAttribute(mma_gemm2, cudaFuncAttributeMaxDynamicSharedMemorySize, SMEM_G2);

    const int GRID = MROWS / 128 / TPC;  // 1024

    zero_kernel<<<1, 256>>>();
    embed_agg_kernel<<<dim3(16, HH, NB), 256>>>(x, embW, embB);
    for (int l = 0; l < 3; l++) {
        int hsel = l & 1;  // l0: g_h, l1: g_h2, l2: g_h
        mma_gemm1<<<GRID, 256, SMEM_G1>>>(W1 + l * 2 * HH * HH, b1 + l * HH, hsel, l * 2);
        mma_gemm2<<<GRID, 256, SMEM_G2>>>(W2 + l * HH * HH, b2 + l * HH,
                                          g1 + l * HH, be1 + l * HH, l * 2, l * 2 + 1);
        if (l < 2)
            fused_res_agg<<<dim3(4, HH, NB), 256>>>(hsel, g2 + l * HH, be2 + l * HH,
                                                    l * 2 + 1);
        else
            relu_pool<<<dim3(4, HH, NB), 256>>>(hsel, g2 + l * HH, be2 + l * HH,
                                                l * 2 + 1);
    }
    head_kernel<<<1, 256>>>(hW1, hb1, hW2, hb2, out);
}

// round 17
// speedup vs baseline: 1.1245x; 1.0946x over previous
#include <cuda_runtime.h>
#include <cuda_fp16.h>
#include <cstdint>

#define NB 16
#define NN 32768          // nodes = 128*256 torus
#define HH 64
#define NDOUT 128
#define MROWS (NB*NN)     // 524288
#define EPSBN 1e-5f
#define RB 272            // As row bytes: 256 data + 16 pad -> conflict-free ldmatrix
#define TPC 4

// ---------------- scratch (feature-major layout: [b][f][n]) ----------------
__device__ __half g_h[NB*HH*NN];     // trunk ping
__device__ __half g_h2[NB*HH*NN];    // trunk pong
__device__ __half g_agg[NB*HH*NN];   // stencil aggregate (gemm1 input)
__device__ __half g_y[NB*HH*NN];     // gemm outputs (pre-BN), fp16; stats from fp32 accs
__device__ float  g_stats[6][2*HH];
__device__ float  g_pool[NB*HH];

// ---------------- helpers ---------------------------------------------------
__device__ __forceinline__ float2 h2f(uint32_t u) {
    __half2 h = *(__half2*)&u;
    return __half22float2(h);
}
__device__ __forceinline__ uint32_t f2h(float a, float b) {
    __half2 h = __floats2half2_rn(a, b);
    return *(uint32_t*)&h;
}
__device__ __forceinline__ void u4tof8(uint4 u, float* f) {
    float2 a = h2f(u.x), b = h2f(u.y), c = h2f(u.z), d = h2f(u.w);
    f[0] = a.x; f[1] = a.y; f[2] = b.x; f[3] = b.y;
    f[4] = c.x; f[5] = c.y; f[6] = d.x; f[7] = d.y;
}
__device__ __forceinline__ uint4 f8tou4(const float* f) {
    uint4 u;
    u.x = f2h(f[0], f[1]); u.y = f2h(f[2], f[3]);
    u.z = f2h(f[4], f[5]); u.w = f2h(f[6], f[7]);
    return u;
}
__device__ __forceinline__ void mma_f16(float* d, const uint4& a, uint32_t b0, uint32_t b1) {
    asm volatile(
        "mma.sync.aligned.m16n8k16.row.col.f32.f16.f16.f32 "
        "{%0,%1,%2,%3}, {%4,%5,%6,%7}, {%8,%9}, {%0,%1,%2,%3};"
        : "+f"(d[0]), "+f"(d[1]), "+f"(d[2]), "+f"(d[3])
        : "r"(a.x), "r"(a.y), "r"(a.z), "r"(a.w), "r"(b0), "r"(b1));
}
#define LDMX4T(r0, r1, r2, r3, addr) \
    asm volatile("ldmatrix.sync.aligned.m8n8.x4.trans.shared.b16 {%0,%1,%2,%3}, [%4];" \
        : "=r"(r0), "=r"(r1), "=r"(r2), "=r"(r3) : "r"(addr))
__device__ __forceinline__ void bn_coef(int use, int f, const float* g, const float* be,
                                        float& sc, float& sh) {
    const float invM = 1.f / (float)MROWS;
    float s = g_stats[use][f], q = g_stats[use][HH + f];
    float m = s * invM;
    float v = q * invM - m * m;
    float r = rsqrtf(v + EPSBN);
    sc = g[f] * r;
    sh = fmaf(-m, sc, be[f]);
}
__device__ __forceinline__ void cpa16(uint32_t dst, const void* src) {
    asm volatile("cp.async.cg.shared.global [%0], [%1], 16;" :: "r"(dst), "l"(src));
}
__device__ __forceinline__ void cpcommit() { asm volatile("cp.async.commit_group;"); }
__device__ __forceinline__ void cpwait(int n) {
    switch (n) {
        case 0: asm volatile("cp.async.wait_group 0;"); break;
        case 1: asm volatile("cp.async.wait_group 1;"); break;
        case 2: asm volatile("cp.async.wait_group 2;"); break;
        default: asm volatile("cp.async.wait_group 3;"); break;
    }
}

// ---------------- small kernels ---------------------------------------------
__global__ void zero_kernel() {
    int tid = threadIdx.x;
    float* s = &g_stats[0][0];
    for (int i = tid; i < 6 * 2 * HH; i += 256) s[i] = 0.f;
    for (int i = tid; i < NB * HH; i += 256) g_pool[i] = 0.f;
}

// h[b][f][n] = relu(sum_c x[b][c][n] W[c][f] + b[f]) -> fp16
__global__ void embed_kernel(const float* __restrict__ x,
                             const float* __restrict__ W,
                             const float* __restrict__ bias) {
    int b = blockIdx.z, f = blockIdx.y;
    float w0 = W[f], w1 = W[HH + f], w2 = W[2 * HH + f], bb = bias[f];
    int n = blockIdx.x * 2048 + threadIdx.x * 8;
    const float* xb = x + (size_t)(b * 3) * NN + n;
    float r[8];
#pragma unroll
    for (int h = 0; h < 2; h++) {
        float4 a = *(const float4*)(xb + h * 4);
        float4 c = *(const float4*)(xb + NN + h * 4);
        float4 d = *(const float4*)(xb + 2 * NN + h * 4);
        r[h*4+0] = fmaxf(fmaf(a.x, w0, fmaf(c.x, w1, fmaf(d.x, w2, bb))), 0.f);
        r[h*4+1] = fmaxf(fmaf(a.y, w0, fmaf(c.y, w1, fmaf(d.y, w2, bb))), 0.f);
        r[h*4+2] = fmaxf(fmaf(a.z, w0, fmaf(c.z, w1, fmaf(d.z, w2, bb))), 0.f);
        r[h*4+3] = fmaxf(fmaf(a.w, w0, fmaf(c.w, w1, fmaf(d.w, w2, bb))), 0.f);
    }
    *(uint4*)(g_h + (size_t)(b * HH + f) * NN + n) = f8tou4(r);
}

// initial aggregate from g_h (layer 0)
__global__ void agg_kernel() {
    int b = blockIdx.z, f = blockIdx.y;
    const __half* hp = g_h + (size_t)(b * HH + f) * NN;
    int n = blockIdx.x * 2048 + threadIdx.x * 8;
    uint4 u8 = *(const uint4*)(hp + ((n + 256) & 32767));
    uint4 d8 = *(const uint4*)(hp + ((n - 256) & 32767));
    uint4 c8 = *(const uint4*)(hp + n);
    float lf = __half2float(hp[((n & 255) == 0) ? n + 255 : n - 1]);
    float rt = __half2float(hp[(((n + 7) & 255) == 255) ? n - 248 : n + 8]);
    float u[8], d[8], c[8], o[8];
    u4tof8(u8, u); u4tof8(d8, d); u4tof8(c8, c);
#pragma unroll
    for (int j = 0; j < 8; j++) {
        float L = (j == 0) ? lf : c[j - 1];
        float R = (j == 7) ? rt : c[j + 1];
        o[j] = 0.25f * (u[j] + d[j] + L + R);
    }
    *(uint4*)(g_agg + (size_t)(b * HH + f) * NN + n) = f8tou4(o);
}

// ---------------- fused: h_out = h_in + relu(bn(y)); agg = stencil(h_out) ---
__global__ __launch_bounds__(256) void fused_res_agg(int hselIn,
                                                     const float* __restrict__ gamma,
                                                     const float* __restrict__ beta,
                                                     int use) {
    __shared__ float hb[8704];
    __shared__ float ss[2];
    int b = blockIdx.z, f = blockIdx.y, tid = threadIdx.x;
    if (tid == 0) {
        float sc, sh;
        bn_coef(use, f, gamma, beta, sc, sh);
        ss[0] = sc; ss[1] = sh;
    }
    __syncthreads();
    float sc = ss[0], sh = ss[1];
    const __half* hin = hselIn ? g_h2 : g_h;
    __half* hout = hselIn ? g_h : g_h2;
    size_t plane = (size_t)(b * HH + f) * NN;
    int n0 = blockIdx.x * 8192;

    for (int q8 = tid; q8 < 1088; q8 += 256) {
        int nh = (n0 - 256 + q8 * 8) & 32767;
        float hf[8], yf[8];
        u4tof8(*(const uint4*)(hin + plane + nh), hf);
        u4tof8(*(const uint4*)(g_y + plane + nh), yf);
#pragma unroll
        for (int j = 0; j < 8; j++) hf[j] += fmaxf(fmaf(yf[j], sc, sh), 0.f);
        *(float4*)&hb[q8 * 8] = make_float4(hf[0], hf[1], hf[2], hf[3]);
        *(float4*)&hb[q8 * 8 + 4] = make_float4(hf[4], hf[5], hf[6], hf[7]);
        if (q8 >= 32 && q8 < 1056) *(uint4*)(hout + plane + nh) = f8tou4(hf);
    }
    __syncthreads();
    for (int q8 = tid; q8 < 1024; q8 += 256) {
        int i = 256 + q8 * 8;
        int n = n0 + q8 * 8;
        float o[8];
#pragma unroll
        for (int j = 0; j < 8; j++) {
            int zj = (n + j) & 255;
            int rowbase = i + j - zj;
            float lf = hb[rowbase + ((zj + 255) & 255)];
            float rt = hb[rowbase + ((zj + 1) & 255)];
            o[j] = 0.25f * (hb[i + j - 256] + hb[i + j + 256] + lf + rt);
        }
        *(uint4*)(g_agg + plane + n) = f8tou4(o);
    }
}

// ---------------- final layer: pool(h_in + relu(bn(y))), no h write ---------
__global__ __launch_bounds__(256) void relu_pool(int hselIn,
                                                 const float* __restrict__ gamma,
                                                 const float* __restrict__ beta,
                                                 int use) {
    __shared__ float ss[2];
    __shared__ float wsum[8];
    int b = blockIdx.z, f = blockIdx.y, tid = threadIdx.x;
    if (tid == 0) {
        float sc, sh;
        bn_coef(use, f, gamma, beta, sc, sh);
        ss[0] = sc; ss[1] = sh;
    }
    __syncthreads();
    float sc = ss[0], sh = ss[1];
    const __half* hin = hselIn ? g_h2 : g_h;
    size_t plane = (size_t)(b * HH + f) * NN;
    int n0 = blockIdx.x * 8192;
    float ps = 0.f;
    for (int q8 = tid; q8 < 1024; q8 += 256) {
        int n = n0 + q8 * 8;
        float hf[8], yf[8];
        u4tof8(*(const uint4*)(hin + plane + n), hf);
        u4tof8(*(const uint4*)(g_y + plane + n), yf);
#pragma unroll
        for (int j = 0; j < 8; j++) ps += hf[j] + fmaxf(fmaf(yf[j], sc, sh), 0.f);
    }
#pragma unroll
    for (int off = 16; off; off >>= 1) ps += __shfl_down_sync(0xffffffffu, ps, off);
    if ((tid & 31) == 0) wsum[tid >> 5] = ps;
    __syncthreads();
    if (tid == 0) {
        float t = 0.f;
#pragma unroll
        for (int w = 0; w < 8; w++) t += wsum[w];
        atomicAdd(&g_pool[b * HH + f], t);
    }
}

__global__ void head_kernel(const float* __restrict__ W1, const float* __restrict__ b1,
                            const float* __restrict__ W2, const float* __restrict__ b2,
                            float* __restrict__ out) {
    __shared__ float z[NB * HH];
    int tid = threadIdx.x;
    const float invN = 1.f / (float)NN;
    for (int idx = tid; idx < NB * HH; idx += 256) {
        int b = idx >> 6, j = idx & 63;
        float acc = b1[j];
#pragma unroll
        for (int k = 0; k < HH; k++)
            acc = fmaf(g_pool[b * HH + k] * invN, W1[k * HH + j], acc);
        z[idx] = fmaxf(acc, 0.f);
    }
    __syncthreads();
    for (int idx = tid; idx < NB * NDOUT; idx += 256) {
        int b = idx >> 7, o = idx & 127;
        float acc = b2[o];
#pragma unroll
        for (int j = 0; j < HH; j++)
            acc = fmaf(z[b * HH + j], W2[j * NDOUT + o], acc);
        out[idx] = acc;
    }
}

// ---------------- GEMM1: y = W1^T @ [h ; agg], K=128, fp16, cp.async --------
// (verified R13 version: single-buffered, 3 CTAs/SM)
__global__ __launch_bounds__(256) void mma_gemm1(const float* __restrict__ W,
                                                 const float* __restrict__ bias,
                                                 int hsel, int useOut) {
    extern __shared__ char smem[];
    float* bias_s = (float*)smem;
    uint4* Wp = (uint4*)(smem + 1024);                // [4 fq][8 ks16][32] = 16KB
    char* As = smem + 1024 + 16384;                   // 128 rows x RB
    const uint32_t As_u = (uint32_t)__cvta_generic_to_shared(As);

    const int tid = threadIdx.x, lid = tid & 31, wid = tid >> 5;
    const int r = lid >> 2, cq = lid & 3;
    const int mq = wid & 1, nq = wid >> 1;
    const __half* hbase = hsel ? g_h2 : g_h;

    if (tid < 64) bias_s[tid] = bias[tid];
    for (int e = tid; e < 1024; e += 256) {
        int lane = e & 31, ks16 = (e >> 5) & 7, fq = e >> 8;
        int er = lane >> 2, ec = lane & 3;
        int m0 = fq * 16, k0 = ks16 * 16;
        uint4 w;
        w.x = f2h(W[(k0 + 2*ec)     * HH + m0 + er], W[(k0 + 2*ec + 1) * HH + m0 + er]);
        w.y = f2h(W[(k0 + 2*ec)     * HH + m0 + 8 + er], W[(k0 + 2*ec + 1) * HH + m0 + 8 + er]);
        w.z = f2h(W[(k0 + 2*ec + 8) * HH + m0 + er], W[(k0 + 2*ec + 9) * HH + m0 + er]);
        w.w = f2h(W[(k0 + 2*ec + 8) * HH + m0 + 8 + er], W[(k0 + 2*ec + 9) * HH + m0 + 8 + er]);
        Wp[e] = w;
    }

    float st[2][2] = {{0.f, 0.f}, {0.f, 0.f}};
    float sq[2][2] = {{0.f, 0.f}, {0.f, 0.f}};

    // prologue: issue all 4 chunks of tile 0
    {
        int T = blockIdx.x * TPC;
        int b = T >> 8, n0 = (T & 255) << 7;
        for (int c = 0; c < 4; c++) {
#pragma unroll
            for (int i = 0; i < 2; i++) {
                int idx = tid + i * 256;
                int k = c * 32 + (idx >> 4), n8 = idx & 15;
                const __half* src = ((k < HH) ? hbase : g_agg) +
                                    ((size_t)(b * HH + (k & 63))) * NN + n0 + n8 * 8;
                cpa16(As_u + (uint32_t)(k * RB + n8 * 16), src);
            }
            cpcommit();
        }
    }
    __syncthreads();   // bias_s/Wp fills visible before acc init

    for (int t = 0; t < TPC; t++) {
        int T = blockIdx.x * TPC + t;
        int b = T >> 8, n0 = (T & 255) << 7;

        float acc[2][4][4];
        {
            float b0 = bias_s[mq * 32 + r],       b1v = bias_s[mq * 32 + 8 + r];
            float b2v = bias_s[mq * 32 + 16 + r], b3 = bias_s[mq * 32 + 24 + r];
#pragma unroll
            for (int nt = 0; nt < 4; nt++) {
                acc[0][nt][0] = b0;  acc[0][nt][1] = b0;
                acc[0][nt][2] = b1v; acc[0][nt][3] = b1v;
                acc[1][nt][0] = b2v; acc[1][nt][1] = b2v;
                acc[1][nt][2] = b3;  acc[1][nt][3] = b3;
            }
        }

        for (int c = 0; c < 4; c++) {
            cpwait(3 - c);
            __syncthreads();
#pragma unroll
            for (int j = 0; j < 2; j++) {
                int ks16 = c * 2 + j;
                uint4 A0 = Wp[((mq * 2 + 0) * 8 + ks16) * 32 + lid];
                uint4 A1 = Wp[((mq * 2 + 1) * 8 + ks16) * 32 + lid];
                uint32_t rowa = As_u + (uint32_t)((ks16 * 16 + (lid & 15)) * RB +
                                (nq * 32 + (lid >> 4) * 8) * 2);
                uint32_t b0, b1, b2, b3, b4, b5, b6, b7;
                LDMX4T(b0, b1, b2, b3, rowa);
                LDMX4T(b4, b5, b6, b7, rowa + 32);
                mma_f16(acc[0][0], A0, b0, b1); mma_f16(acc[1][0], A1, b0, b1);
                mma_f16(acc[0][1], A0, b2, b3); mma_f16(acc[1][1], A1, b2, b3);
                mma_f16(acc[0][2], A0, b4, b5); mma_f16(acc[1][2], A1, b4, b5);
                mma_f16(acc[0][3], A0, b6, b7); mma_f16(acc[1][3], A1, b6, b7);
            }
        }
        __syncthreads();

        if (t + 1 < TPC) {
            int T2 = T + 1;
            int b2 = T2 >> 8, n02 = (T2 & 255) << 7;
            for (int c = 0; c < 4; c++) {
#pragma unroll
                for (int i = 0; i < 2; i++) {
                    int idx = tid + i * 256;
                    int k = c * 32 + (idx >> 4), n8 = idx & 15;
                    const __half* src = ((k < HH) ? hbase : g_agg) +
                                        ((size_t)(b2 * HH + (k & 63))) * NN + n02 + n8 * 8;
                    cpa16(As_u + (uint32_t)(k * RB + n8 * 16), src);
                }
                cpcommit();
            }
        }

#pragma unroll
        for (int f = 0; f < 2; f++) {
            size_t base0 = ((size_t)(b * HH + mq * 32 + f * 16 + r)) * NN + n0 + nq * 32;
            size_t base1 = base0 + (size_t)8 * NN;
#pragma unroll
            for (int nt = 0; nt < 4; nt++) {
                int nn = nt * 8 + 2 * cq;
                *(uint32_t*)(g_y + base0 + nn) = f2h(acc[f][nt][0], acc[f][nt][1]);
                *(uint32_t*)(g_y + base1 + nn) = f2h(acc[f][nt][2], acc[f][nt][3]);
                st[f][0] += acc[f][nt][0] + acc[f][nt][1];
                sq[f][0] += acc[f][nt][0] * acc[f][nt][0] + acc[f][nt][1] * acc[f][nt][1];
                st[f][1] += acc[f][nt][2] + acc[f][nt][3];
                sq[f][1] += acc[f][nt][2] * acc[f][nt][2] + acc[f][nt][3] * acc[f][nt][3];
            }
        }
    }

#pragma unroll
    for (int d = 1; d < 4; d <<= 1)
#pragma unroll
        for (int f = 0; f < 2; f++)
#pragma unroll
            for (int hv = 0; hv < 2; hv++) {
                st[f][hv] += __shfl_xor_sync(0xffffffffu, st[f][hv], d);
                sq[f][hv] += __shfl_xor_sync(0xffffffffu, sq[f][hv], d);
            }
    if (cq == 0)
#pragma unroll
        for (int f = 0; f < 2; f++) {
            int m = mq * 32 + f * 16 + r;
            atomicAdd(&g_stats[useOut][m], st[f][0]);
            atomicAdd(&g_stats[useOut][HH + m], sq[f][0]);
            atomicAdd(&g_stats[useOut][m + 8], st[f][1]);
            atomicAdd(&g_stats[useOut][HH + m + 8], sq[f][1]);
        }
}

// ---------------- GEMM2: y = W2^T @ relu(bn(y)), K=64, fp16, reg-pipelined --
// R13 version + __launch_bounds__(256,3): cap regs at 84 -> 3 CTAs/SM
__global__ __launch_bounds__(256, 3) void mma_gemm2(const float* __restrict__ W,
                                                    const float* __restrict__ bias,
                                                    const float* __restrict__ gamma,
                                                    const float* __restrict__ beta,
                                                    int useIn, int useOut) {
    extern __shared__ char smem[];
    float* bias_s = (float*)smem;
    float* sc_s   = (float*)(smem + 256);
    float* sh_s   = (float*)(smem + 512);
    uint4* Wp = (uint4*)(smem + 1024);                // [4 fq][4 ks16][32] = 8KB
    char* As = smem + 1024 + 8192;                    // 64 rows x RB

    const int tid = threadIdx.x, lid = tid & 31, wid = tid >> 5;
    const int r = lid >> 2, cq = lid & 3;
    const int mq = wid & 1, nq = wid >> 1;
    const uint32_t As_u = (uint32_t)__cvta_generic_to_shared(As);

    if (tid < 64) bias_s[tid] = bias[tid];
    if (tid >= 64 && tid < 128) {
        float sc, sh;
        bn_coef(useIn, tid - 64, gamma, beta, sc, sh);
        sc_s[tid - 64] = sc; sh_s[tid - 64] = sh;
    }
    for (int e = tid; e < 512; e += 256) {
        int lane = e & 31, ks16 = (e >> 5) & 3, fq = e >> 7;
        int er = lane >> 2, ec = lane & 3;
        int m0 = fq * 16, k0 = ks16 * 16;
        uint4 w;
        w.x = f2h(W[(k0 + 2*ec)     * HH + m0 + er], W[(k0 + 2*ec + 1) * HH + m0 + er]);
        w.y = f2h(W[(k0 + 2*ec)     * HH + m0 + 8 + er], W[(k0 + 2*ec + 1) * HH + m0 + 8 + er]);
        w.z = f2h(W[(k0 + 2*ec + 8) * HH + m0 + er], W[(k0 + 2*ec + 9) * HH + m0 + er]);
        w.w = f2h(W[(k0 + 2*ec + 8) * HH + m0 + 8 + er], W[(k0 + 2*ec + 9) * HH + m0 + 8 + er]);
        Wp[e] = w;
    }
    __syncthreads();   // bias_s/sc_s/sh_s/Wp ready

    float st[2][2] = {{0.f, 0.f}, {0.f, 0.f}};
    float sq[2][2] = {{0.f, 0.f}, {0.f, 0.f}};

    uint4 pfA[2], pfB[2];
    auto loadc = [&](int t, int c, uint4* pf) {
        int T = blockIdx.x * TPC + t;
        int b = T >> 8, n0 = (T & 255) << 7;
#pragma unroll
        for (int i = 0; i < 2; i++) {
            int idx = tid + i * 256;
            int k = c * 32 + (idx >> 4), n8 = idx & 15;
            pf[i] = *(const uint4*)(g_y + ((size_t)(b * HH + k)) * NN + n0 + n8 * 8);
        }
    };
    auto stsc = [&](int c, const uint4* pf) {
#pragma unroll
        for (int i = 0; i < 2; i++) {
            int idx = tid + i * 256;
            int k = c * 32 + (idx >> 4), n8 = idx & 15;
            float sc = sc_s[k], sh = sh_s[k];
            float v[8];
            u4tof8(pf[i], v);
#pragma unroll
            for (int j = 0; j < 8; j++) v[j] = fmaxf(fmaf(v[j], sc, sh), 0.f);
            *(uint4*)(As + k * RB + n8 * 16) = f8tou4(v);
        }
    };
    auto mmachunk = [&](int c, float acc[2][4][4]) {
#pragma unroll
        for (int j = 0; j < 2; j++) {
            int ks16 = c * 2 + j;
            uint4 A0 = Wp[((mq * 2 + 0) * 4 + ks16) * 32 + lid];
            uint4 A1 = Wp[((mq * 2 + 1) * 4 + ks16) * 32 + lid];
            uint32_t rowa = As_u + (uint32_t)((ks16 * 16 + (lid & 15)) * RB +
                            (nq * 32 + (lid >> 4) * 8) * 2);
            uint32_t b0, b1, b2, b3, b4, b5, b6, b7;
            LDMX4T(b0, b1, b2, b3, rowa);
            LDMX4T(b4, b5, b6, b7, rowa + 32);
            mma_f16(acc[0][0], A0, b0, b1); mma_f16(acc[1][0], A1, b0, b1);
            mma_f16(acc[0][1], A0, b2, b3); mma_f16(acc[1][1], A1, b2, b3);
            mma_f16(acc[0][2], A0, b4, b5); mma_f16(acc[1][2], A1, b4, b5);
            mma_f16(acc[0][3], A0, b6, b7); mma_f16(acc[1][3], A1, b6, b7);
        }
    };

    loadc(0, 0, pfA);
    for (int t = 0; t < TPC; t++) {
        int T = blockIdx.x * TPC + t;
        int b = T >> 8, n0 = (T & 255) << 7;

        stsc(0, pfA);
        loadc(t, 1, pfB);
        __syncthreads();            // chunk 0 visible

        float acc[2][4][4];
        {
            float b0 = bias_s[mq * 32 + r],       b1v = bias_s[mq * 32 + 8 + r];
            float b2v = bias_s[mq * 32 + 16 + r], b3 = bias_s[mq * 32 + 24 + r];
#pragma unroll
            for (int nt = 0; nt < 4; nt++) {
                acc[0][nt][0] = b0;  acc[0][nt][1] = b0;
                acc[0][nt][2] = b1v; acc[0][nt][3] = b1v;
                acc[1][nt][0] = b2v; acc[1][nt][1] = b2v;
                acc[1][nt][2] = b3;  acc[1][nt][3] = b3;
            }
        }

        mmachunk(0, acc);
        stsc(1, pfB);               // disjoint region: safe during chunk-0 MMAs
        if (t + 1 < TPC) loadc(t + 1, 0, pfA);
        __syncthreads();            // chunk 1 visible + chunk-0 reads done
        mmachunk(1, acc);

#pragma unroll
        for (int f = 0; f < 2; f++) {
            size_t base0 = ((size_t)(b * HH + mq * 32 + f * 16 + r)) * NN + n0 + nq * 32;
            size_t base1 = base0 + (size_t)8 * NN;
#pragma unroll
            for (int nt = 0; nt < 4; nt++) {
                int nn = nt * 8 + 2 * cq;
                *(uint32_t*)(g_y + base0 + nn) = f2h(acc[f][nt][0], acc[f][nt][1]);
                *(uint32_t*)(g_y + base1 + nn) = f2h(acc[f][nt][2], acc[f][nt][3]);
                st[f][0] += acc[f][nt][0] + acc[f][nt][1];
                sq[f][0] += acc[f][nt][0] * acc[f][nt][0] + acc[f][nt][1] * acc[f][nt][1];
                st[f][1] += acc[f][nt][2] + acc[f][nt][3];
                sq[f][1] += acc[f][nt][2] * acc[f][nt][2] + acc[f][nt][3] * acc[f][nt][3];
            }
        }
        __syncthreads();            // As reads done before next tile's STS
    }

#pragma unroll
    for (int d = 1; d < 4; d <<= 1)
#pragma unroll
        for (int f = 0; f < 2; f++)
#pragma unroll
            for (int hv = 0; hv < 2; hv++) {
                st[f][hv] += __shfl_xor_sync(0xffffffffu, st[f][hv], d);
                sq[f][hv] += __shfl_xor_sync(0xffffffffu, sq[f][hv], d);
            }
    if (cq == 0)
#pragma unroll
        for (int f = 0; f < 2; f++) {
            int m = mq * 32 + f * 16 + r;
            atomicAdd(&g_stats[useOut][m], st[f][0]);
            atomicAdd(&g_stats[useOut][HH + m], sq[f][0]);
            atomicAdd(&g_stats[useOut][m + 8], st[f][1]);
            atomicAdd(&g_stats[useOut][HH + m + 8], sq[f][1]);
        }
}

// ---------------- driver ---------------------------------------------------
extern "C" void kernel_launch(void* const* d_in, const int* in_sizes, int n_in,
                              void* d_out, int out_size) {
    const float* x    = (const float*)d_in[0];
    const float* embW = (const float*)d_in[2];
    const float* embB = (const float*)d_in[3];
    const float* W1   = (const float*)d_in[4];
    const float* b1   = (const float*)d_in[5];
    const float* g1   = (const float*)d_in[6];
    const float* be1  = (const float*)d_in[7];
    const float* W2   = (const float*)d_in[8];
    const float* b2   = (const float*)d_in[9];
    const float* g2   = (const float*)d_in[10];
    const float* be2  = (const float*)d_in[11];
    const float* hW1  = (const float*)d_in[12];
    const float* hb1  = (const float*)d_in[13];
    const float* hW2  = (const float*)d_in[14];
    const float* hb2  = (const float*)d_in[15];
    float* out = (float*)d_out;

    const int SMEM_G1 = 1024 + 16384 + 128 * RB;  // 52224
    const int SMEM_G2 = 1024 + 8192 + 64 * RB;    // 26624
    cudaFuncSetAttribute(mma_gemm1, cudaFuncAttributeMaxDynamicSharedMemorySize, SMEM_G1);
    cudaFuncSetAttribute(mma_gemm2, cudaFuncAttributeMaxDynamicSharedMemorySize, SMEM_G2);

    const int GRID = MROWS / 128 / TPC;  // 1024

    zero_kernel<<<1, 256>>>();
    embed_kernel<<<dim3(16, HH, NB), 256>>>(x, embW, embB);
    agg_kernel<<<dim3(16, HH, NB), 256>>>();
    for (int l = 0; l < 3; l++) {
        int hsel = l & 1;  // l0: g_h, l1: g_h2, l2: g_h
        mma_gemm1<<<GRID, 256, SMEM_G1>>>(W1 + l * 2 * HH * HH, b1 + l * HH, hsel, l * 2);
        mma_gemm2<<<GRID, 256, SMEM_G2>>>(W2 + l * HH * HH, b2 + l * HH,
                                          g1 + l * HH, be1 + l * HH, l * 2, l * 2 + 1);
        if (l < 2)
            fused_res_agg<<<dim3(4, HH, NB), 256>>>(hsel, g2 + l * HH, be2 + l * HH,
                                                    l * 2 + 1);
        else
            relu_pool<<<dim3(4, HH, NB), 256>>>(hsel, g2 + l * HH, be2 + l * HH,
                                                l * 2 + 1);
    }
    head_kernel<<<1, 256>>>(hW1, hb1, hW2, hb2, out);
}